// round 10
// baseline (speedup 1.0000x reference)
#include <cuda_runtime.h>
#include <cstdint>
#include <math.h>

// ---------------- problem constants ----------------
#define TD      50000
#define E_NO    2000
#define I_NO    500
#define CCH     63
#define TN      200
#define OBS_LEN 401
#define NB      13
#define PI_F    3.14159265358979323846f

typedef unsigned long long u64;

// ---------------- device scratch ----------------
__device__ float g_ek[CCH * TN];
__device__ float g_ik[CCH * TN];
__device__ float g_ok[CCH * (OBS_LEN + 3)];
__device__ float g_syn_e[CCH * TD];
__device__ float g_syn_i[CCH * TD];

// pack two fp32 -> bf16x2 (lo = first, hi = second)
__device__ __forceinline__ uint32_t bf2(float lo, float hi) {
    uint32_t r;
    asm("cvt.rn.bf16x2.f32 %0, %1, %2;" : "=r"(r) : "f"(hi), "f"(lo));
    return r;
}
// packed f32x2 helpers
__device__ __forceinline__ u64 pk(float lo, float hi) {
    u64 r;
    asm("mov.b64 %0, {%1, %2};" : "=l"(r) : "f"(lo), "f"(hi));
    return r;
}
__device__ __forceinline__ void fma2(u64& a, u64 x, u64 w) {
    asm("fma.rn.f32x2 %0, %1, %2, %0;" : "+l"(a) : "l"(x), "l"(w));
}
__device__ __forceinline__ void unpk(float& lo, float& hi, u64 v) {
    asm("mov.b64 {%0, %1}, %2;" : "=f"(lo), "=f"(hi) : "l"(v));
}

// ============================================================
// Kernel 0: build temporal kernels (601 blocks, fp32 MUFU basis)
// ============================================================
__global__ __launch_bounds__(64) void build_kernels_kernel(
    const float* __restrict__ W_syn,   // [63][13][2]
    const float* __restrict__ W_obs)   // [63][25]
{
    __shared__ float bs[NB];
    const int blk = blockIdx.x;
    const int tid = threadIdx.x;

    if (blk < TN) {
        const int j = blk;
        if (tid < NB) {
            float raw = 5.f * logf((float)j + 1.f + 1e-8f);
            float phi = 0.5f * PI_F * (float)tid;
            float v = 0.5f * cosf(raw - phi) + 0.5f;
            if (raw < phi - PI_F || raw > phi + PI_F) v = 0.f;
            bs[tid] = v;
        }
        __syncthreads();
        if (tid < CCH) {
            const int c = tid;
            float ae = 0.f, ai = 0.f;
            #pragma unroll
            for (int b = 0; b < NB; b++) {
                ae = fmaf(W_syn[(c * NB + b) * 2 + 0], bs[b], ae);
                ai = fmaf(W_syn[(c * NB + b) * 2 + 1], bs[b], ai);
            }
            g_ek[c * TN + j] = ae;
            g_ik[c * TN + j] = ai;
        }
    } else {
        const int j = blk - TN;            // 0..400
        if (tid < NB) {
            float xo = (float)(j - TN);
            float raw = 5.f * logf(fabsf(xo) + 1.f + 1e-8f);
            float phi = 0.5f * PI_F * (float)tid;
            float v = 0.5f * cosf(raw - phi) + 0.5f;
            if (raw < phi - PI_F || raw > phi + PI_F) v = 0.f;
            bs[tid] = v;
        }
        __syncthreads();
        if (tid < CCH) {
            const int c = tid;
            float a = W_obs[c * 25 + 0] * bs[0];
            #pragma unroll
            for (int b = 1; b < NB; b++) {
                if (j >= TN) a = fmaf(W_obs[c * 25 + 2 * b - 1], bs[b], a);
                if (j <= TN) a = fmaf(W_obs[c * 25 + 2 * b    ], bs[b], a);
            }
            g_ok[c * (OBS_LEN + 3) + j] = a;
        }
    }
}

// ============================================================
// Kernel 1: bf16 mma.sync GEMM (unchanged from R8 measured config)
// ============================================================
#define GBM     128
#define GBK     32
#define APW     20
#define AW      (128 * APW)
#define BW      (64 * APW)
#define STW     (AW + BW)
#define GSMEM_BYTES (64 * 132 * 4)

__global__ __launch_bounds__(256) void gemm_bf16_kernel(
    const float* __restrict__ Ae, const float* __restrict__ Cse, float* __restrict__ oute,
    const float* __restrict__ Ai, const float* __restrict__ Csi, float* __restrict__ outi)
{
    extern __shared__ float smf[];
    uint32_t* smw = reinterpret_cast<uint32_t*>(smf);

    const float* A; const float* Cs; float* outT; int K;
    if (blockIdx.y == 0) { A = Ae; Cs = Cse; outT = oute; K = E_NO; }
    else                 { A = Ai; Cs = Csi; outT = outi; K = I_NO; }
    const int S = (K + GBK - 1) / GBK;

    const int tid  = threadIdx.x;
    const int wid  = tid >> 5;
    const int lane = tid & 31;
    const int g    = lane >> 2;
    const int t4   = lane & 3;
    const int wm   = (wid & 3) * 32;
    const int wn   = (wid >> 2) * 32;
    const int bm   = blockIdx.x * GBM;

    float acc[2][4][4];
    #pragma unroll
    for (int mi = 0; mi < 2; mi++)
        #pragma unroll
        for (int ni = 0; ni < 4; ni++)
            #pragma unroll
            for (int r = 0; r < 4; r++) acc[mi][ni][r] = 0.f;

    float4 ra[4], rb[2];

    auto ldg_stage = [&](int s) {
        const int k0 = s * GBK;
        #pragma unroll
        for (int j = 0; j < 4; j++) {
            int idx = tid + 256 * j, r = idx >> 3, q = idx & 7, k = k0 + q * 4;
            float4 v = make_float4(0.f, 0.f, 0.f, 0.f);
            if ((bm + r < TD) && (k + 4 <= K))
                v = *reinterpret_cast<const float4*>(A + (size_t)(bm + r) * K + k);
            ra[j] = v;
        }
        #pragma unroll
        for (int j = 0; j < 2; j++) {
            int idx = tid + 256 * j, r = idx >> 3, q = idx & 7, k = k0 + q * 4;
            float4 v = make_float4(0.f, 0.f, 0.f, 0.f);
            if ((r < CCH) && (k + 4 <= K))
                v = *reinterpret_cast<const float4*>(Cs + (size_t)(r + 1) * K + k);
            rb[j] = v;
        }
    };
    auto sts_stage = [&](int buf) {
        uint32_t* ab = smw + buf * STW;
        uint32_t* bb = ab + AW;
        #pragma unroll
        for (int j = 0; j < 4; j++) {
            int idx = tid + 256 * j, r = idx >> 3, q = idx & 7;
            uint2* p = reinterpret_cast<uint2*>(ab + r * APW + q * 2);
            *p = make_uint2(bf2(ra[j].x, ra[j].y), bf2(ra[j].z, ra[j].w));
        }
        #pragma unroll
        for (int j = 0; j < 2; j++) {
            int idx = tid + 256 * j, r = idx >> 3, q = idx & 7;
            uint2* p = reinterpret_cast<uint2*>(bb + r * APW + q * 2);
            *p = make_uint2(bf2(rb[j].x, rb[j].y), bf2(rb[j].z, rb[j].w));
        }
    };
    auto compute = [&](int buf) {
        const uint32_t* As = smw + buf * STW;
        const uint32_t* Bs = As + AW;
        #pragma unroll
        for (int ks = 0; ks < 2; ks++) {
            const int kw = ks * 8;
            uint32_t af[2][4];
            #pragma unroll
            for (int mi = 0; mi < 2; mi++) {
                int r = wm + mi * 16 + g;
                af[mi][0] = As[(r)     * APW + kw + t4];
                af[mi][1] = As[(r + 8) * APW + kw + t4];
                af[mi][2] = As[(r)     * APW + kw + 4 + t4];
                af[mi][3] = As[(r + 8) * APW + kw + 4 + t4];
            }
            uint32_t bf[4][2];
            #pragma unroll
            for (int ni = 0; ni < 4; ni++) {
                int n = wn + ni * 8 + g;
                bf[ni][0] = Bs[n * APW + kw + t4];
                bf[ni][1] = Bs[n * APW + kw + 4 + t4];
            }
            #pragma unroll
            for (int mi = 0; mi < 2; mi++)
                #pragma unroll
                for (int ni = 0; ni < 4; ni++) {
                    asm volatile(
                        "mma.sync.aligned.m16n8k16.row.col.f32.bf16.bf16.f32 "
                        "{%0,%1,%2,%3}, {%4,%5,%6,%7}, {%8,%9}, {%0,%1,%2,%3};"
                        : "+f"(acc[mi][ni][0]), "+f"(acc[mi][ni][1]),
                          "+f"(acc[mi][ni][2]), "+f"(acc[mi][ni][3])
                        : "r"(af[mi][0]), "r"(af[mi][1]), "r"(af[mi][2]), "r"(af[mi][3]),
                          "r"(bf[ni][0]), "r"(bf[ni][1]));
                }
        }
    };

    ldg_stage(0);
    sts_stage(0);
    __syncthreads();

    for (int s = 0; s < S; s++) {
        const bool have_next = (s + 1 < S);
        if (have_next) ldg_stage(s + 1);
        compute(s & 1);
        __syncthreads();
        if (have_next) {
            sts_stage((s + 1) & 1);
            __syncthreads();
        }
    }

    #pragma unroll
    for (int mi = 0; mi < 2; mi++)
        #pragma unroll
        for (int ni = 0; ni < 4; ni++) {
            int n0 = wn + ni * 8 + 2 * t4;
            int m0 = wm + mi * 16 + g;
            smf[(n0)     * 132 + m0]     = acc[mi][ni][0];
            smf[(n0 + 1) * 132 + m0]     = acc[mi][ni][1];
            smf[(n0)     * 132 + m0 + 8] = acc[mi][ni][2];
            smf[(n0 + 1) * 132 + m0 + 8] = acc[mi][ni][3];
        }
    __syncthreads();
    for (int idx = tid; idx < 64 * 128; idx += 256) {
        int c  = idx >> 7;
        int tl = idx & 127;
        int t  = bm + tl;
        if (c < CCH && t < TD)
            outT[(size_t)c * TD + t] = smf[c * 132 + tl];
    }
}

// ============================================================
// Kernel 2: convs via packed fma.rn.f32x2 + Gumbel epilogue
//   8 outputs/thread as 4 f32x2 accumulators; window kept as
//   6 even-pairs + 5 odd-pairs; weights duplicated in smem.
// ============================================================
#define TT 2048

__global__ __launch_bounds__(256) void conv_finish_kernel(
    const float* __restrict__ Z,
    const float* __restrict__ u,
    const float* __restrict__ Theta,
    const float* __restrict__ temp_p,
    float* __restrict__ out)
{
    __shared__ __align__(16) float se_s[TT + TN + 16];
    __shared__ __align__(16) float si_s[TT + TN + 16];
    __shared__ __align__(16) float z_s [TT + 2 * TN + 16];
    __shared__ __align__(16) float ek2[2 * TN];           // duplicated (w,w) pairs
    __shared__ __align__(16) float ik2[2 * TN];
    __shared__ __align__(16) float ok2[2 * OBS_LEN + 2];

    const int c   = blockIdx.x;
    const int t0  = blockIdx.y * TT;
    const int tid = threadIdx.x;

    const float* se_g = g_syn_e + (size_t)c * TD;
    const float* si_g = g_syn_i + (size_t)c * TD;

    for (int i = tid; i < TT + TN + 16; i += 256) {
        int t = t0 - (TN - 1) + i;
        float ve = 0.f, vi = 0.f;
        if (t >= 0 && t < TD) { ve = se_g[t]; vi = si_g[t]; }
        se_s[i] = ve; si_s[i] = vi;
    }
    for (int i = tid; i < TT + 2 * TN + 16; i += 256) {
        int t = t0 - TN + i;
        z_s[i] = (t >= 0 && t < TD) ? Z[t] : 0.f;
    }
    for (int j = tid; j < TN; j += 256) {
        float ve = g_ek[c * TN + j];
        float vi = g_ik[c * TN + j];
        ek2[2 * j] = ve; ek2[2 * j + 1] = ve;
        ik2[2 * j] = vi; ik2[2 * j + 1] = vi;
    }
    for (int j = tid; j < OBS_LEN; j += 256) {
        float v = g_ok[c * (OBS_LEN + 3) + j];
        ok2[2 * j] = v; ok2[2 * j + 1] = v;
    }
    __syncthreads();

    const int tl0 = tid * 8;
    u64 acc2[4] = {0ull, 0ull, 0ull, 0ull};

    // ---------- causal e/i convs ----------
    {
        u64 Ee[6], Oe[5], Ei[6], Oi[5];
        float te, ti_;
        {
            float4 f0 = *reinterpret_cast<const float4*>(&se_s[tl0]);
            float4 f1 = *reinterpret_cast<const float4*>(&se_s[tl0 + 4]);
            float4 f2 = *reinterpret_cast<const float4*>(&se_s[tl0 + 8]);
            Ee[0] = pk(f0.x, f0.y); Ee[1] = pk(f0.z, f0.w);
            Ee[2] = pk(f1.x, f1.y); Ee[3] = pk(f1.z, f1.w);
            Ee[4] = pk(f2.x, f2.y); Ee[5] = pk(f2.z, f2.w);
            Oe[0] = pk(f0.y, f0.z); Oe[1] = pk(f0.w, f1.x);
            Oe[2] = pk(f1.y, f1.z); Oe[3] = pk(f1.w, f2.x);
            Oe[4] = pk(f2.y, f2.z);
            te = f2.w;
        }
        {
            float4 f0 = *reinterpret_cast<const float4*>(&si_s[tl0]);
            float4 f1 = *reinterpret_cast<const float4*>(&si_s[tl0 + 4]);
            float4 f2 = *reinterpret_cast<const float4*>(&si_s[tl0 + 8]);
            Ei[0] = pk(f0.x, f0.y); Ei[1] = pk(f0.z, f0.w);
            Ei[2] = pk(f1.x, f1.y); Ei[3] = pk(f1.z, f1.w);
            Ei[4] = pk(f2.x, f2.y); Ei[5] = pk(f2.z, f2.w);
            Oi[0] = pk(f0.y, f0.z); Oi[1] = pk(f0.w, f1.x);
            Oi[2] = pk(f1.y, f1.z); Oi[3] = pk(f1.w, f2.x);
            Oi[4] = pk(f2.y, f2.z);
            ti_ = f2.w;
        }
        #pragma unroll 5
        for (int p = 0; p < 50; p++) {
            // weight pairs: taps 196-4p+dj, dj=0..3 (each duplicated)
            ulonglong2 wea = *reinterpret_cast<const ulonglong2*>(&ek2[392 - 8 * p]);
            ulonglong2 wia = *reinterpret_cast<const ulonglong2*>(&ik2[392 - 8 * p]);
            ulonglong2 web = *reinterpret_cast<const ulonglong2*>(&ek2[396 - 8 * p]);
            ulonglong2 wib = *reinterpret_cast<const ulonglong2*>(&ik2[396 - 8 * p]);
            float4 ne = *reinterpret_cast<const float4*>(&se_s[tl0 + 12 + 4 * p]);
            float4 ni = *reinterpret_cast<const float4*>(&si_s[tl0 + 12 + 4 * p]);
            #pragma unroll
            for (int m = 0; m < 4; m++) {
                fma2(acc2[m], Oe[1 + m], wea.x);   // dj=0, base 3
                fma2(acc2[m], Ee[1 + m], wea.y);   // dj=1, base 2
                fma2(acc2[m], Oe[m],     web.x);   // dj=2, base 1
                fma2(acc2[m], Ee[m],     web.y);   // dj=3, base 0
                fma2(acc2[m], Oi[1 + m], wia.x);
                fma2(acc2[m], Ei[1 + m], wia.y);
                fma2(acc2[m], Oi[m],     wib.x);
                fma2(acc2[m], Ei[m],     wib.y);
            }
            // slide window by 4
            Ee[0] = Ee[2]; Ee[1] = Ee[3]; Ee[2] = Ee[4]; Ee[3] = Ee[5];
            Ee[4] = pk(ne.x, ne.y); Ee[5] = pk(ne.z, ne.w);
            Oe[0] = Oe[2]; Oe[1] = Oe[3]; Oe[2] = Oe[4];
            Oe[3] = pk(te, ne.x); Oe[4] = pk(ne.y, ne.z); te = ne.w;
            Ei[0] = Ei[2]; Ei[1] = Ei[3]; Ei[2] = Ei[4]; Ei[3] = Ei[5];
            Ei[4] = pk(ni.x, ni.y); Ei[5] = pk(ni.z, ni.w);
            Oi[0] = Oi[2]; Oi[1] = Oi[3]; Oi[2] = Oi[4];
            Oi[3] = pk(ti_, ni.x); Oi[4] = pk(ni.y, ni.z); ti_ = ni.w;
        }
    }

    // ---------- obs conv ----------
    {
        u64 E[6], O[5];
        float tz;
        {
            float4 f0 = *reinterpret_cast<const float4*>(&z_s[tl0]);
            float4 f1 = *reinterpret_cast<const float4*>(&z_s[tl0 + 4]);
            float4 f2 = *reinterpret_cast<const float4*>(&z_s[tl0 + 8]);
            E[0] = pk(f0.x, f0.y); E[1] = pk(f0.z, f0.w);
            E[2] = pk(f1.x, f1.y); E[3] = pk(f1.z, f1.w);
            E[4] = pk(f2.x, f2.y); E[5] = pk(f2.z, f2.w);
            O[0] = pk(f0.y, f0.z); O[1] = pk(f0.w, f1.x);
            O[2] = pk(f1.y, f1.z); O[3] = pk(f1.w, f2.x);
            O[4] = pk(f2.y, f2.z);
            tz = f2.w;
        }
        {   // tail tap j=400 -> base 0
            u64 w400 = *reinterpret_cast<const u64*>(&ok2[800]);
            #pragma unroll
            for (int m = 0; m < 4; m++) fma2(acc2[m], E[m], w400);
        }
        #pragma unroll 5
        for (int p = 0; p < 100; p++) {
            // taps 396-4p+dj; bases: dj=0->4, 1->3, 2->2, 3->1
            ulonglong2 wa = *reinterpret_cast<const ulonglong2*>(&ok2[792 - 8 * p]);
            ulonglong2 wb = *reinterpret_cast<const ulonglong2*>(&ok2[796 - 8 * p]);
            float4 nz = *reinterpret_cast<const float4*>(&z_s[tl0 + 12 + 4 * p]);
            #pragma unroll
            for (int m = 0; m < 4; m++) {
                fma2(acc2[m], E[2 + m], wa.x);   // dj=0, base 4
                fma2(acc2[m], O[1 + m], wa.y);   // dj=1, base 3
                fma2(acc2[m], E[1 + m], wb.x);   // dj=2, base 2
                fma2(acc2[m], O[m],     wb.y);   // dj=3, base 1
            }
            E[0] = E[2]; E[1] = E[3]; E[2] = E[4]; E[3] = E[5];
            E[4] = pk(nz.x, nz.y); E[5] = pk(nz.z, nz.w);
            O[0] = O[2]; O[1] = O[3]; O[2] = O[4];
            O[3] = pk(tz, nz.x); O[4] = pk(nz.y, nz.z); tz = nz.w;
        }
    }

    // ---------- epilogue ----------
    float acc[8];
    #pragma unroll
    for (int m = 0; m < 4; m++) unpk(acc[2 * m], acc[2 * m + 1], acc2[m]);

    const float th   = Theta[c];
    const float temp = *temp_p;
    #pragma unroll
    for (int i = 0; i < 8; i++) {
        int t = t0 + tl0 + i;
        if (t < TD) {
            float L0 = acc[i] + th;
            float2 uv = *reinterpret_cast<const float2*>(&u[((size_t)t * CCH + c) * 2]);
            float g0 = -logf(-logf(uv.x + 1e-8f) + 1e-8f);
            float g1 = -logf(-logf(uv.y + 1e-8f) + 1e-8f);
            float zh = 1.f / (1.f + expf(-((L0 + g0 - g1) / temp)));
            float sg = 1.f / (1.f + expf(-L0));
            out[(size_t)t * CCH + c]                    = zh;
            out[(size_t)TD * CCH + (size_t)t * CCH + c] = sg;
        }
    }
}

// ============================================================
// launch
// ============================================================
extern "C" void kernel_launch(void* const* d_in, const int* in_sizes, int n_in,
                              void* d_out, int out_size)
{
    const float* S_e    = (const float*)d_in[0];
    const float* S_i    = (const float*)d_in[1];
    const float* Z_obs  = (const float*)d_in[2];
    const float* temp   = (const float*)d_in[3];
    const float* u      = (const float*)d_in[4];
    const float* C_se   = (const float*)d_in[5];
    const float* C_si   = (const float*)d_in[6];
    const float* W_syn  = (const float*)d_in[7];
    const float* W_obs  = (const float*)d_in[8];
    const float* Theta  = (const float*)d_in[9];
    float* out = (float*)d_out;
    (void)in_sizes; (void)n_in; (void)out_size;

    cudaFuncSetAttribute(gemm_bf16_kernel, cudaFuncAttributeMaxDynamicSharedMemorySize, GSMEM_BYTES);

    float* syn_e_ptr; float* syn_i_ptr;
    cudaGetSymbolAddress((void**)&syn_e_ptr, g_syn_e);
    cudaGetSymbolAddress((void**)&syn_i_ptr, g_syn_i);

    build_kernels_kernel<<<TN + OBS_LEN, 64>>>(W_syn, W_obs);

    dim3 gg((TD + GBM - 1) / GBM, 2);          // 391 x 2 (E and I fused)
    gemm_bf16_kernel<<<gg, 256, GSMEM_BYTES>>>(S_e, C_se, syn_e_ptr,
                                               S_i, C_si, syn_i_ptr);

    dim3 cg(CCH, (TD + TT - 1) / TT);          // 63 x 25
    conv_finish_kernel<<<cg, 256>>>(Z_obs, u, Theta, temp, out);
}

// round 12
// speedup vs baseline: 1.1537x; 1.1537x over previous
#include <cuda_runtime.h>
#include <cstdint>
#include <math.h>

// ---------------- problem constants ----------------
#define TD      50000
#define E_NO    2000
#define I_NO    500
#define CCH     63
#define TN      200
#define OBS_LEN 401
#define NB      13
#define PI_F    3.14159265358979323846f
#define TT      2048
#define NTILE   25                         // ceil(TD/TT)
#define TDP     (NTILE * TT)               // 51200 padded stride

// ---------------- device scratch ----------------
__device__ float g_ek[CCH * TN];
__device__ float g_ik[CCH * TN];
__device__ float g_ok[CCH * (OBS_LEN + 3)];
__device__ float g_syn_e[CCH * TD];
__device__ float g_syn_i[CCH * TD];
__device__ float g_zf[CCH * TDP];          // obs-conv result, padded

// pack two fp32 -> bf16x2
__device__ __forceinline__ uint32_t bf2(float lo, float hi) {
    uint32_t r;
    asm("cvt.rn.bf16x2.f32 %0, %1, %2;" : "=r"(r) : "f"(hi), "f"(lo));
    return r;
}

// ============================================================
// Kernel 0: build temporal kernels (601 blocks, fp32 MUFU basis)
// ============================================================
__global__ __launch_bounds__(64) void build_kernels_kernel(
    const float* __restrict__ W_syn,   // [63][13][2]
    const float* __restrict__ W_obs)   // [63][25]
{
    __shared__ float bs[NB];
    const int blk = blockIdx.x;
    const int tid = threadIdx.x;

    if (blk < TN) {
        const int j = blk;
        if (tid < NB) {
            float raw = 5.f * logf((float)j + 1.f + 1e-8f);
            float phi = 0.5f * PI_F * (float)tid;
            float v = 0.5f * cosf(raw - phi) + 0.5f;
            if (raw < phi - PI_F || raw > phi + PI_F) v = 0.f;
            bs[tid] = v;
        }
        __syncthreads();
        if (tid < CCH) {
            const int c = tid;
            float ae = 0.f, ai = 0.f;
            #pragma unroll
            for (int b = 0; b < NB; b++) {
                ae = fmaf(W_syn[(c * NB + b) * 2 + 0], bs[b], ae);
                ai = fmaf(W_syn[(c * NB + b) * 2 + 1], bs[b], ai);
            }
            g_ek[c * TN + j] = ae;
            g_ik[c * TN + j] = ai;
        }
    } else {
        const int j = blk - TN;            // 0..400
        if (tid < NB) {
            float xo = (float)(j - TN);
            float raw = 5.f * logf(fabsf(xo) + 1.f + 1e-8f);
            float phi = 0.5f * PI_F * (float)tid;
            float v = 0.5f * cosf(raw - phi) + 0.5f;
            if (raw < phi - PI_F || raw > phi + PI_F) v = 0.f;
            bs[tid] = v;
        }
        __syncthreads();
        if (tid < CCH) {
            const int c = tid;
            float a = W_obs[c * 25 + 0] * bs[0];
            #pragma unroll
            for (int b = 1; b < NB; b++) {
                if (j >= TN) a = fmaf(W_obs[c * 25 + 2 * b - 1], bs[b], a);
                if (j <= TN) a = fmaf(W_obs[c * 25 + 2 * b    ], bs[b], a);
            }
            g_ok[c * (OBS_LEN + 3) + j] = a;
        }
    }
}

// ============================================================
// Kernel 1 (fused): y<2 -> bf16 mma GEMM (E or I); y==2 -> obs conv
//   GEMM: BM=128,BN=64,BK=32, 8 warps 4x2, m16n8k16 bf16 (R8 measured)
//   obs:  1575 blocks (c = x%63, tile = x/63), scalar sliding window,
//         runs on the fma pipe the HBM-bound GEMM leaves idle.
// ============================================================
#define GBM     128
#define GBK     32
#define APW     20
#define AW      (128 * APW)
#define BW      (64 * APW)
#define STW     (AW + BW)
#define GSMEM_BYTES (64 * 132 * 4)         // 33792 B

#define GEMM_GX 391                        // ceil(TD/GBM)
#define OBS_GX  (CCH * NTILE)              // 1575

__global__ __launch_bounds__(256) void gemm_obs_kernel(
    const float* __restrict__ Ae, const float* __restrict__ Cse, float* __restrict__ oute,
    const float* __restrict__ Ai, const float* __restrict__ Csi, float* __restrict__ outi,
    const float* __restrict__ Z)
{
    extern __shared__ float smf[];
    const int tid = threadIdx.x;

    if (blockIdx.y == 2) {
        // ================== obs conv branch ==================
        const int c  = blockIdx.x % CCH;
        const int t0 = (blockIdx.x / CCH) * TT;

        float* z_s  = smf;                       // TT + 2*TN + 16
        float* ok_s = smf + (TT + 2 * TN + 16);  // OBS_LEN + 3

        for (int i = tid; i < TT + 2 * TN + 16; i += 256) {
            int t = t0 - TN + i;
            z_s[i] = (t >= 0 && t < TD) ? Z[t] : 0.f;
        }
        for (int j = tid; j < OBS_LEN; j += 256)
            ok_s[j] = g_ok[c * (OBS_LEN + 3) + j];
        __syncthreads();

        const int tl0 = tid * 8;
        float acc[8];
        #pragma unroll
        for (int i = 0; i < 8; i++) acc[i] = 0.f;

        float zw[12];
        #pragma unroll
        for (int x = 0; x < 3; x++) {
            float4 a = *reinterpret_cast<const float4*>(&z_s[tl0 + 4 * x]);
            zw[4 * x] = a.x; zw[4 * x + 1] = a.y; zw[4 * x + 2] = a.z; zw[4 * x + 3] = a.w;
        }
        {   // tail tap j = 400 -> z index tl0 + i
            float w = ok_s[400];
            #pragma unroll
            for (int i = 0; i < 8; i++) acc[i] = fmaf(zw[i], w, acc[i]);
        }
        #pragma unroll 5
        for (int p = 0; p < 100; p++) {
            float4 w4 = *reinterpret_cast<const float4*>(&ok_s[396 - 4 * p]);
            float4 nz = *reinterpret_cast<const float4*>(&z_s[tl0 + 12 + 4 * p]);
            const float w[4] = {w4.x, w4.y, w4.z, w4.w};
            #pragma unroll
            for (int dj = 0; dj < 4; dj++) {
                #pragma unroll
                for (int i = 0; i < 8; i++)
                    acc[i] = fmaf(zw[i + 4 - dj], w[dj], acc[i]);
            }
            #pragma unroll
            for (int x = 0; x < 8; x++) zw[x] = zw[x + 4];
            zw[8] = nz.x; zw[9] = nz.y; zw[10] = nz.z; zw[11] = nz.w;
        }

        // padded store: no guard needed
        float4* dst = reinterpret_cast<float4*>(&g_zf[(size_t)c * TDP + t0 + tl0]);
        dst[0] = make_float4(acc[0], acc[1], acc[2], acc[3]);
        dst[1] = make_float4(acc[4], acc[5], acc[6], acc[7]);
        return;
    }

    // ================== GEMM branch ==================
    if (blockIdx.x >= GEMM_GX) return;

    uint32_t* smw = reinterpret_cast<uint32_t*>(smf);

    const float* A; const float* Cs; float* outT; int K;
    if (blockIdx.y == 0) { A = Ae; Cs = Cse; outT = oute; K = E_NO; }
    else                 { A = Ai; Cs = Csi; outT = outi; K = I_NO; }
    const int S = (K + GBK - 1) / GBK;

    const int wid  = tid >> 5;
    const int lane = tid & 31;
    const int g    = lane >> 2;
    const int t4   = lane & 3;
    const int wm   = (wid & 3) * 32;
    const int wn   = (wid >> 2) * 32;
    const int bm   = blockIdx.x * GBM;

    float acc[2][4][4];
    #pragma unroll
    for (int mi = 0; mi < 2; mi++)
        #pragma unroll
        for (int ni = 0; ni < 4; ni++)
            #pragma unroll
            for (int r = 0; r < 4; r++) acc[mi][ni][r] = 0.f;

    float4 ra[4], rb[2];

    auto ldg_stage = [&](int s) {
        const int k0 = s * GBK;
        #pragma unroll
        for (int j = 0; j < 4; j++) {
            int idx = tid + 256 * j, r = idx >> 3, q = idx & 7, k = k0 + q * 4;
            float4 v = make_float4(0.f, 0.f, 0.f, 0.f);
            if ((bm + r < TD) && (k + 4 <= K))
                v = *reinterpret_cast<const float4*>(A + (size_t)(bm + r) * K + k);
            ra[j] = v;
        }
        #pragma unroll
        for (int j = 0; j < 2; j++) {
            int idx = tid + 256 * j, r = idx >> 3, q = idx & 7, k = k0 + q * 4;
            float4 v = make_float4(0.f, 0.f, 0.f, 0.f);
            if ((r < CCH) && (k + 4 <= K))
                v = *reinterpret_cast<const float4*>(Cs + (size_t)(r + 1) * K + k);
            rb[j] = v;
        }
    };
    auto sts_stage = [&](int buf) {
        uint32_t* ab = smw + buf * STW;
        uint32_t* bb = ab + AW;
        #pragma unroll
        for (int j = 0; j < 4; j++) {
            int idx = tid + 256 * j, r = idx >> 3, q = idx & 7;
            uint2* p = reinterpret_cast<uint2*>(ab + r * APW + q * 2);
            *p = make_uint2(bf2(ra[j].x, ra[j].y), bf2(ra[j].z, ra[j].w));
        }
        #pragma unroll
        for (int j = 0; j < 2; j++) {
            int idx = tid + 256 * j, r = idx >> 3, q = idx & 7;
            uint2* p = reinterpret_cast<uint2*>(bb + r * APW + q * 2);
            *p = make_uint2(bf2(rb[j].x, rb[j].y), bf2(rb[j].z, rb[j].w));
        }
    };
    auto compute = [&](int buf) {
        const uint32_t* As = smw + buf * STW;
        const uint32_t* Bs = As + AW;
        #pragma unroll
        for (int ks = 0; ks < 2; ks++) {
            const int kw = ks * 8;
            uint32_t af[2][4];
            #pragma unroll
            for (int mi = 0; mi < 2; mi++) {
                int r = wm + mi * 16 + g;
                af[mi][0] = As[(r)     * APW + kw + t4];
                af[mi][1] = As[(r + 8) * APW + kw + t4];
                af[mi][2] = As[(r)     * APW + kw + 4 + t4];
                af[mi][3] = As[(r + 8) * APW + kw + 4 + t4];
            }
            uint32_t bf[4][2];
            #pragma unroll
            for (int ni = 0; ni < 4; ni++) {
                int n = wn + ni * 8 + g;
                bf[ni][0] = Bs[n * APW + kw + t4];
                bf[ni][1] = Bs[n * APW + kw + 4 + t4];
            }
            #pragma unroll
            for (int mi = 0; mi < 2; mi++)
                #pragma unroll
                for (int ni = 0; ni < 4; ni++) {
                    asm volatile(
                        "mma.sync.aligned.m16n8k16.row.col.f32.bf16.bf16.f32 "
                        "{%0,%1,%2,%3}, {%4,%5,%6,%7}, {%8,%9}, {%0,%1,%2,%3};"
                        : "+f"(acc[mi][ni][0]), "+f"(acc[mi][ni][1]),
                          "+f"(acc[mi][ni][2]), "+f"(acc[mi][ni][3])
                        : "r"(af[mi][0]), "r"(af[mi][1]), "r"(af[mi][2]), "r"(af[mi][3]),
                          "r"(bf[ni][0]), "r"(bf[ni][1]));
                }
        }
    };

    ldg_stage(0);
    sts_stage(0);
    __syncthreads();

    for (int s = 0; s < S; s++) {
        const bool have_next = (s + 1 < S);
        if (have_next) ldg_stage(s + 1);
        compute(s & 1);
        __syncthreads();
        if (have_next) {
            sts_stage((s + 1) & 1);
            __syncthreads();
        }
    }

    #pragma unroll
    for (int mi = 0; mi < 2; mi++)
        #pragma unroll
        for (int ni = 0; ni < 4; ni++) {
            int n0 = wn + ni * 8 + 2 * t4;
            int m0 = wm + mi * 16 + g;
            smf[(n0)     * 132 + m0]     = acc[mi][ni][0];
            smf[(n0 + 1) * 132 + m0]     = acc[mi][ni][1];
            smf[(n0)     * 132 + m0 + 8] = acc[mi][ni][2];
            smf[(n0 + 1) * 132 + m0 + 8] = acc[mi][ni][3];
        }
    __syncthreads();
    for (int idx = tid; idx < 64 * 128; idx += 256) {
        int c  = idx >> 7;
        int tl = idx & 127;
        int t  = bm + tl;
        if (c < CCH && t < TD)
            outT[(size_t)c * TD + t] = smf[c * 132 + tl];
    }
}

// ============================================================
// Kernel 2: e/i convs (sliding register window) + zf + epilogue
// ============================================================
__global__ __launch_bounds__(256) void conv_finish_kernel(
    const float* __restrict__ u,
    const float* __restrict__ Theta,
    const float* __restrict__ temp_p,
    float* __restrict__ out)
{
    __shared__ __align__(16) float se_s[TT + TN + 16];
    __shared__ __align__(16) float si_s[TT + TN + 16];
    __shared__ __align__(16) float ek_s[TN];
    __shared__ __align__(16) float ik_s[TN];

    const int c   = blockIdx.x;        // channel fastest
    const int t0  = blockIdx.y * TT;
    const int tid = threadIdx.x;

    const float* se_g = g_syn_e + (size_t)c * TD;
    const float* si_g = g_syn_i + (size_t)c * TD;

    for (int i = tid; i < TT + TN + 16; i += 256) {
        int t = t0 - (TN - 1) + i;
        float ve = 0.f, vi = 0.f;
        if (t >= 0 && t < TD) { ve = se_g[t]; vi = si_g[t]; }
        se_s[i] = ve; si_s[i] = vi;
    }
    for (int j = tid; j < TN; j += 256) {
        ek_s[j] = g_ek[c * TN + j];
        ik_s[j] = g_ik[c * TN + j];
    }
    __syncthreads();

    const int tl0 = tid * 8;
    float acc[8];
    // init with obs-conv result (padded scratch: unguarded float4 loads OK)
    {
        const float4* zf = reinterpret_cast<const float4*>(&g_zf[(size_t)c * TDP + t0 + tl0]);
        float4 a = zf[0], b = zf[1];
        acc[0] = a.x; acc[1] = a.y; acc[2] = a.z; acc[3] = a.w;
        acc[4] = b.x; acc[5] = b.y; acc[6] = b.z; acc[7] = b.w;
    }

    // ---------- causal e/i convs (sliding register window) ----------
    {
        float ew[12], iw[12];
        #pragma unroll
        for (int x = 0; x < 3; x++) {
            float4 a = *reinterpret_cast<const float4*>(&se_s[tl0 + 4 * x]);
            float4 b = *reinterpret_cast<const float4*>(&si_s[tl0 + 4 * x]);
            ew[4 * x] = a.x; ew[4 * x + 1] = a.y; ew[4 * x + 2] = a.z; ew[4 * x + 3] = a.w;
            iw[4 * x] = b.x; iw[4 * x + 1] = b.y; iw[4 * x + 2] = b.z; iw[4 * x + 3] = b.w;
        }
        #pragma unroll 5
        for (int p = 0; p < 50; p++) {
            float4 we4 = *reinterpret_cast<const float4*>(&ek_s[196 - 4 * p]);
            float4 wi4 = *reinterpret_cast<const float4*>(&ik_s[196 - 4 * p]);
            float4 ne  = *reinterpret_cast<const float4*>(&se_s[tl0 + 12 + 4 * p]);
            float4 ni  = *reinterpret_cast<const float4*>(&si_s[tl0 + 12 + 4 * p]);
            const float we[4] = {we4.x, we4.y, we4.z, we4.w};
            const float wi[4] = {wi4.x, wi4.y, wi4.z, wi4.w};
            #pragma unroll
            for (int dj = 0; dj < 4; dj++) {
                #pragma unroll
                for (int i = 0; i < 8; i++) {
                    acc[i] = fmaf(ew[i + 3 - dj], we[dj], acc[i]);
                    acc[i] = fmaf(iw[i + 3 - dj], wi[dj], acc[i]);
                }
            }
            #pragma unroll
            for (int x = 0; x < 8; x++) { ew[x] = ew[x + 4]; iw[x] = iw[x + 4]; }
            ew[8] = ne.x; ew[9] = ne.y; ew[10] = ne.z; ew[11] = ne.w;
            iw[8] = ni.x; iw[9] = ni.y; iw[10] = ni.z; iw[11] = ni.w;
        }
    }

    // ---------- epilogue ----------
    const float th   = Theta[c];
    const float temp = *temp_p;
    #pragma unroll
    for (int i = 0; i < 8; i++) {
        int t = t0 + tl0 + i;
        if (t < TD) {
            float L0 = acc[i] + th;
            float2 uv = *reinterpret_cast<const float2*>(&u[((size_t)t * CCH + c) * 2]);
            float g0 = -logf(-logf(uv.x + 1e-8f) + 1e-8f);
            float g1 = -logf(-logf(uv.y + 1e-8f) + 1e-8f);
            float zh = 1.f / (1.f + expf(-((L0 + g0 - g1) / temp)));
            float sg = 1.f / (1.f + expf(-L0));
            out[(size_t)t * CCH + c]                    = zh;
            out[(size_t)TD * CCH + (size_t)t * CCH + c] = sg;
        }
    }
}

// ============================================================
// launch
// ============================================================
extern "C" void kernel_launch(void* const* d_in, const int* in_sizes, int n_in,
                              void* d_out, int out_size)
{
    const float* S_e    = (const float*)d_in[0];
    const float* S_i    = (const float*)d_in[1];
    const float* Z_obs  = (const float*)d_in[2];
    const float* temp   = (const float*)d_in[3];
    const float* u      = (const float*)d_in[4];
    const float* C_se   = (const float*)d_in[5];
    const float* C_si   = (const float*)d_in[6];
    const float* W_syn  = (const float*)d_in[7];
    const float* W_obs  = (const float*)d_in[8];
    const float* Theta  = (const float*)d_in[9];
    float* out = (float*)d_out;
    (void)in_sizes; (void)n_in; (void)out_size;

    cudaFuncSetAttribute(gemm_obs_kernel, cudaFuncAttributeMaxDynamicSharedMemorySize, GSMEM_BYTES);

    float* syn_e_ptr; float* syn_i_ptr;
    cudaGetSymbolAddress((void**)&syn_e_ptr, g_syn_e);
    cudaGetSymbolAddress((void**)&syn_i_ptr, g_syn_i);

    build_kernels_kernel<<<TN + OBS_LEN, 64>>>(W_syn, W_obs);

    dim3 gg(OBS_GX, 3);                // x: 1575; y: 0=E gemm, 1=I gemm, 2=obs conv
    gemm_obs_kernel<<<gg, 256, GSMEM_BYTES>>>(S_e, C_se, syn_e_ptr,
                                              S_i, C_si, syn_i_ptr, Z_obs);

    dim3 cg(CCH, NTILE);               // 63 x 25
    conv_finish_kernel<<<cg, 256>>>(u, Theta, temp, out);
}